// round 12
// baseline (speedup 1.0000x reference)
#include <cuda_runtime.h>
#include <cuda_fp16.h>
#include <cstdint>
#include <cstddef>

#define THREADS 768
#define M_TOT (64 * 64 * 32)

// X converted to fp16, same layout as X: [d1][d2][b][k]
__device__ __half g_xh[(size_t)M_TOT * 64];   // 16.8 MB

// ---------------- smem layout (bytes) ----------------
// RING01: [R:8][slot:4][word:2][cell:16][lane:32] u32; word0=(f0,f1) word1=(i,o)
// RINGC : [R:8][slot:4][cell:16][lpair:16] u32 = (c@2k, c@2k+1)
#define RC_OFF    131072u
#define W_OFF     163840u      // [g*32+n][72 halves] fp16 (x0.5)
#define A_OFF     186880u      // 8 warps * 16 cells * 72 halves fp16
#define BIAS_OFF  205312u      // [g:5][n:32] f32 (x0.5)
#define GPROG_OFF 205952u
#define READY_OFF 205984u
#define SHS_OFF   206048u
#define SHH_OFF   214240u
#define SM_TOTAL  222432

// ---------------- helpers ----------------
__device__ __forceinline__ uint32_t smem_u32(const void* p) {
    uint32_t a;
    asm("{ .reg .u64 t; cvta.to.shared.u64 t, %1; cvt.u32.u64 %0, t; }"
        : "=r"(a) : "l"(p));
    return a;
}
__device__ __forceinline__ void ldsm_x4(uint32_t& r0, uint32_t& r1,
                                        uint32_t& r2, uint32_t& r3,
                                        uint32_t addr) {
    asm volatile("ldmatrix.sync.aligned.m8n8.x4.shared.b16 {%0,%1,%2,%3}, [%4];"
                 : "=r"(r0), "=r"(r1), "=r"(r2), "=r"(r3) : "r"(addr));
}
__device__ __forceinline__ void mma_f16(float* d, const uint32_t* a,
                                        uint32_t b0, uint32_t b1) {
    asm volatile(
        "mma.sync.aligned.m16n8k16.row.col.f32.f16.f16.f32 "
        "{%0,%1,%2,%3}, {%4,%5,%6,%7}, {%8,%9}, {%0,%1,%2,%3};"
        : "+f"(d[0]), "+f"(d[1]), "+f"(d[2]), "+f"(d[3])
        : "r"(a[0]), "r"(a[1]), "r"(a[2]), "r"(a[3]), "r"(b0), "r"(b1));
}
__device__ __forceinline__ uint32_t h1(float v) {
    __half h = __float2half_rn(v);
    return (uint32_t)(*reinterpret_cast<unsigned short*>(&h));
}
__device__ __forceinline__ uint32_t packh2(float a, float b) {
    __half2 h = __floats2half2_rn(a, b);
    return *reinterpret_cast<uint32_t*>(&h);
}
__device__ __forceinline__ float2 up2(uint32_t w) {
    __half2 h = *reinterpret_cast<__half2*>(&w);
    return __half22float2(h);
}
__device__ __forceinline__ float tanhapx(float x) {
    float y;
    asm("tanh.approx.f32 %0, %1;" : "=f"(y) : "f"(x));
    return y;
}
__device__ __forceinline__ float sigs(float a) {   // arg pre-scaled by 0.5
    return fmaf(0.5f, tanhapx(a), 0.5f);
}

#define SPIN_GE(addr, target) do {                                          \
    int _v;                                                                 \
    asm volatile("ld.acquire.cta.shared.b32 %0, [%1];"                      \
                 : "=r"(_v) : "r"(addr) : "memory");                        \
    while (_v < (target)) {                                                 \
        asm volatile("nanosleep.u32 32;");                                  \
        asm volatile("ld.acquire.cta.shared.b32 %0, [%1];"                  \
                     : "=r"(_v) : "r"(addr) : "memory");                    \
    }                                                                       \
} while (0)
#define ST_REL(addr, val)                                                   \
    asm volatile("st.release.cta.shared.b32 [%0], %1;"                      \
                 :: "r"(addr), "r"(val) : "memory")
#define STS32(addr, val)                                                    \
    asm volatile("st.shared.b32 [%0], %1;" :: "r"(addr), "r"(val) : "memory")
#define STSV2(addr, v0, v1)                                                 \
    asm volatile("st.shared.v2.b32 [%0], {%1, %2};"                         \
                 :: "r"(addr), "r"(v0), "r"(v1) : "memory")
#define CPA16(dst, src)                                                     \
    asm volatile("cp.async.ca.shared.global [%0], [%1], 16;"                \
                 :: "r"(dst), "l"(src) : "memory")

struct UC {
    float uf00, uf01, uf10, uf11;
    float ui0, ui1, uo0, uo1, uc0, uc1;
};

// gates from packed ring words (x0.5-scaled; u halved)
__device__ __forceinline__ void cell_g(uint32_t a01, uint32_t ac, int lodd,
                                       const UC& u,
                                       float hup, float hl,
                                       float sup, float sl,
                                       float& s, float& h)
{
    uint32_t w0, w1, wcv;
    asm volatile("ld.shared.b32 %0, [%1];" : "=r"(w0) : "r"(a01));
    asm volatile("ld.shared.b32 %0, [%1];" : "=r"(w1) : "r"(a01 + 2048u));
    asm volatile("ld.shared.b32 %0, [%1];" : "=r"(wcv) : "r"(ac));
    float2 qa = up2(w0);    // (f0, f1)
    float2 qb = up2(w1);    // (i, o)
    float2 qc = up2(wcv);   // (c_even, c_odd)
    float qcv = lodd ? qc.y : qc.x;
    float a0 = fmaf(u.uf01, hl, fmaf(u.uf00, hup, qa.x));
    float a1 = fmaf(u.uf11, hl, fmaf(u.uf10, hup, qa.y));
    float a2 = fmaf(u.ui1,  hl, fmaf(u.ui0,  hup, qb.x));
    float a3 = fmaf(u.uo1,  hl, fmaf(u.uo0,  hup, qb.y));
    float a4 = fmaf(u.uc1,  hl, fmaf(u.uc0,  hup, qcv));
    float f0 = sigs(a0), f1 = sigs(a1);
    float ig = sigs(a2), og_ = sigs(a3), cg = sigs(a4);
    s = fmaf(f0, sup, fmaf(f1, sl, ig * cg));
    h = og_ * tanhapx(s);
}

// ================= pre-kernel: X fp32 -> fp16 =================
__global__ void __launch_bounds__(512, 4) xconv(const float* __restrict__ X) {
    size_t i = ((size_t)blockIdx.x * 512 + threadIdx.x) * 4;
    float4 v = *(const float4*)(X + i);
    uint2 p;
    p.x = packh2(v.x, v.y);
    p.y = packh2(v.z, v.w);
    *(uint2*)((char*)g_xh + i * 2) = p;
}

// ================= fused persistent kernel =================
__global__ void __launch_bounds__(THREADS, 1) mdlstm_fused(
    const float* __restrict__ wf, const float* __restrict__ uf,
    const float* __restrict__ biasf,
    const float* __restrict__ wi, const float* __restrict__ ui,
    const float* __restrict__ biasi,
    const float* __restrict__ wo, const float* __restrict__ uo,
    const float* __restrict__ biaso,
    const float* __restrict__ wc, const float* __restrict__ uc,
    const float* __restrict__ biasc,
    float* __restrict__ out)
{
    extern __shared__ __align__(16) char sm[];
    const uint32_t sbase = smem_u32(sm);
    const int tid  = threadIdx.x;
    const int lane = tid & 31;
    const int w    = tid >> 5;
    const int b    = blockIdx.x >> 2;
    const int og   = blockIdx.x & 3;

    // ---- init: W fp16 x0.5 transposed [n][k], bias f32 x0.5, flags ----
    for (int i = tid; i < 5120; i += THREADS) {
        int g  = i >> 10;
        int r  = i & 1023;
        int n  = r >> 5;
        int kp = r & 31;
        const float* W = (g == 0) ? wf : (g == 1) ? (wf + 64 * 128)
                       : (g == 2) ? wi : (g == 3) ? wo : wc;
        float w0 = 0.5f * __ldg(W + (size_t)(2 * kp) * 128 + og * 32 + n);
        float w1 = 0.5f * __ldg(W + (size_t)(2 * kp + 1) * 128 + og * 32 + n);
        uint32_t v = h1(w0) | (h1(w1) << 16);
        STS32(sbase + W_OFF + (uint32_t)(((g * 32 + n) * 72 + 2 * kp) * 2), v);
    }
    for (int i = tid; i < 160; i += THREADS) {
        int g = i >> 5, n = i & 31;
        const float* B = (g == 0) ? biasf : (g == 1) ? (biasf + 128)
                       : (g == 2) ? biasi : (g == 3) ? biaso : biasc;
        float bv = 0.5f * __ldg(B + og * 32 + n);
        asm volatile("st.shared.f32 [%0], %1;"
                     :: "r"(sbase + BIAS_OFF + (uint32_t)(i * 4)), "f"(bv)
                     : "memory");
    }
    if (tid < 8)  *(int*)(sm + GPROG_OFF + tid * 4) = -1;
    if (tid < 16) *(int*)(sm + READY_OFF + tid * 4) = -1;
    __syncthreads();

    if (w < 16) {
        // ========================= REC role =========================
        const int R    = w >> 1;
        const int jb   = (w & 1) * 4;
        const int o    = og * 32 + lane;
        const int lodd = lane & 1;

        UC u;   // halved (tanh half-angle sigmoid)
        u.uf00 = 0.5f * uf[o];        u.uf01 = 0.5f * uf[128 + o];
        u.uf10 = 0.5f * uf[256 + o];  u.uf11 = 0.5f * uf[384 + o];
        u.ui0  = 0.5f * ui[o];        u.ui1  = 0.5f * ui[128 + o];
        u.uo0  = 0.5f * uo[o];        u.uo1  = 0.5f * uo[128 + o];
        u.uc0  = 0.5f * uc[o];        u.uc1  = 0.5f * uc[128 + o];

        float* outb = out + b * 128 + o;
        float* ob0 = outb + (size_t)((4 * w + 0) * 64) * 4096;
        float* ob1 = outb + (size_t)((4 * w + 1) * 64) * 4096;
        float* ob2 = outb + (size_t)((4 * w + 2) * 64) * 4096;
        float* ob3 = outb + (size_t)((4 * w + 3) * 64) * 4096;

        const uint32_t rb01 = sbase + (uint32_t)(R * 16384) + (uint32_t)(lane * 4);
        const uint32_t rbc  = sbase + RC_OFF + (uint32_t)(R * 4096)
                            + (uint32_t)((lane >> 1) * 4);
        const uint32_t r_prev = sbase + READY_OFF + (uint32_t)((w - 1) * 4);
        const uint32_t r_next = sbase + READY_OFF + (uint32_t)((w + 1) * 4);
        const uint32_t r_self = sbase + READY_OFF + (uint32_t)(w * 4);
        const uint32_t gpR    = sbase + GPROG_OFF + (uint32_t)(R * 4);

        float sj0 = 0.f, sj1 = 0.f, sj2 = 0.f, sj3 = 0.f;
        float hj0 = 0.f, hj1 = 0.f, hj2 = 0.f, hj3 = 0.f;

#pragma unroll 1
        for (int s = 0; s <= 66; s++) {
            if (s <= 63) SPIN_GE(gpR, s);

            float sup = 0.f, hup = 0.f;
            if (w > 0 && s <= 63) {
                SPIN_GE(r_prev, s + 3);
                int ps = (s + 3) & 3;
                sup = *(float*)(sm + SHS_OFF
                      + (uint32_t)(((ps * 16 + (w - 1)) * 32 + lane) * 4));
                hup = *(float*)(sm + SHH_OFF
                      + (uint32_t)(((ps * 16 + (w - 1)) * 32 + lane) * 4));
            }

            float os0 = sj0, oh0 = hj0;
            float os1 = sj1, oh1 = hj1;
            float os2 = sj2, oh2 = hj2;

            if (s <= 63) {
                int c = s;
                int cell = (jb + 0) * 2 + (c & 1);
                uint32_t so = (uint32_t)(((c >> 1) & 3));
                float sv, hv;
                cell_g(rb01 + so * 4096 + (uint32_t)(cell * 128),
                       rbc + so * 1024 + (uint32_t)(cell * 64),
                       lodd, u, hup, hj0, sup, sj0, sv, hv);
                *ob0 = sv; ob0 += 4096;
                sj0 = sv; hj0 = hv;
            }
            if (s >= 1 && s <= 64) {
                int c = s - 1;
                int cell = (jb + 1) * 2 + (c & 1);
                uint32_t so = (uint32_t)(((c >> 1) & 3));
                float sv, hv;
                cell_g(rb01 + so * 4096 + (uint32_t)(cell * 128),
                       rbc + so * 1024 + (uint32_t)(cell * 64),
                       lodd, u, oh0, hj1, os0, sj1, sv, hv);
                *ob1 = sv; ob1 += 4096;
                sj1 = sv; hj1 = hv;
            }
            if (s >= 2 && s <= 65) {
                int c = s - 2;
                int cell = (jb + 2) * 2 + (c & 1);
                uint32_t so = (uint32_t)(((c >> 1) & 3));
                float sv, hv;
                cell_g(rb01 + so * 4096 + (uint32_t)(cell * 128),
                       rbc + so * 1024 + (uint32_t)(cell * 64),
                       lodd, u, oh1, hj2, os1, sj2, sv, hv);
                *ob2 = sv; ob2 += 4096;
                sj2 = sv; hj2 = hv;
            }
            if (s >= 3 && s <= 66) {
                int c = s - 3;
                int cell = (jb + 3) * 2 + (c & 1);
                uint32_t so = (uint32_t)(((c >> 1) & 3));
                float sv, hv;
                cell_g(rb01 + so * 4096 + (uint32_t)(cell * 128),
                       rbc + so * 1024 + (uint32_t)(cell * 64),
                       lodd, u, oh2, hj3, os2, sj3, sv, hv);
                *ob3 = sv; ob3 += 4096;
                sj3 = sv; hj3 = hv;
                if (w < 15) {
                    if (s - 7 >= 0) SPIN_GE(r_next, s - 7);
                    int slot = s & 3;
                    *(float*)(sm + SHS_OFF
                        + (uint32_t)(((slot * 16 + w) * 32 + lane) * 4)) = sv;
                    *(float*)(sm + SHH_OFF
                        + (uint32_t)(((slot * 16 + w) * 32 + lane) * 4)) = hv;
                }
            }

            __syncwarp();
            if (lane == 0) ST_REL(r_self, s);
        }
    } else {
        // ========================= GEMM role =========================
        const int R = w - 16;
        const int qr = lane >> 2;
        const int qc = (lane & 3) * 2;
        const int cell = lane >> 1;     // 0..15
        const int half = lane & 1;
        const int j  = cell >> 1;
        const int e  = cell & 1;

        // cp.async: per thread 4x16B; src base for pair P = xbase + P*8192
        const char* xbase = (const char*)g_xh
            + ((size_t)((8 * R + j) * 64) * 32 + (size_t)b) * 128
            + (size_t)e * 4096 + (size_t)half * 64;
        const uint32_t dstb = sbase + A_OFF + (uint32_t)(R * 2304)
                            + (uint32_t)(cell * 144 + half * 64);

        const uint32_t aB = sbase + A_OFF + (uint32_t)(R * 2304)
                          + (uint32_t)((lane & 15) * 144 + (lane >> 4) * 16);
        const uint32_t bB = sbase + W_OFF
                          + (uint32_t)((lane & 15) * 144 + (lane >> 4) * 16);
        const uint32_t rd0 = sbase + READY_OFF + (uint32_t)((2 * R) * 4);
        const uint32_t rd1 = rd0 + 4;
        const uint32_t ring01 = sbase + (uint32_t)(R * 16384);
        const uint32_t ringc  = sbase + RC_OFF + (uint32_t)(R * 4096);

        // prologue prefetch: pair 0
#pragma unroll
        for (int q = 0; q < 4; q++)
            CPA16(dstb + (uint32_t)(q * 16), xbase + q * 16);
        asm volatile("cp.async.commit_group;" ::: "memory");

#pragma unroll 1
        for (int P = 0; P < 32; P++) {
            if (P >= 4) {
                SPIN_GE(rd0, 2 * P - 4);
                SPIN_GE(rd1, 2 * P - 4);
            }
            asm volatile("cp.async.wait_group 0;" ::: "memory");
            __syncwarp();

            // A fragments (reused across gates)
            uint32_t aF[4][4];
#pragma unroll
            for (int ks = 0; ks < 4; ks++)
                ldsm_x4(aF[ks][0], aF[ks][1], aF[ks][2], aF[ks][3],
                        aB + (uint32_t)(ks * 32));

            const uint32_t s01 = ring01 + (uint32_t)((P & 3) * 4096);
            const uint32_t sc  = ringc  + (uint32_t)((P & 3) * 1024);

#pragma unroll 1
            for (int pr = 0; pr < 3; pr++) {
                const int gA = 2 * pr;
                const bool hasB = (pr < 2);
                float accA[4][4], accB[4][4];
#pragma unroll
                for (int ni = 0; ni < 4; ni++)
#pragma unroll
                    for (int e2 = 0; e2 < 4; e2++) {
                        accA[ni][e2] = 0.f; accB[ni][e2] = 0.f;
                    }

#pragma unroll
                for (int ks = 0; ks < 4; ks++) {
#pragma unroll
                    for (int q = 0; q < 2; q++) {
                        uint32_t b0, b1, b2, b3;
                        ldsm_x4(b0, b1, b2, b3,
                                bB + (uint32_t)((gA * 32 + q * 16) * 144 + ks * 32));
                        mma_f16(accA[2 * q],     aF[ks], b0, b2);
                        mma_f16(accA[2 * q + 1], aF[ks], b1, b3);
                        if (hasB) {
                            uint32_t c0, c1, c2, c3;
                            ldsm_x4(c0, c1, c2, c3,
                                    bB + (uint32_t)(((gA + 1) * 32 + q * 16) * 144 + ks * 32));
                            mma_f16(accB[2 * q],     aF[ks], c0, c2);
                            mma_f16(accB[2 * q + 1], aF[ks], c1, c3);
                        }
                    }
                }

                // prefetch next pair right after aF fully consumed (pr==0)
                if (pr == 0) {
                    int Pn = (P < 31) ? P + 1 : 31;
                    const char* xs = xbase + (size_t)Pn * 8192;
#pragma unroll
                    for (int q = 0; q < 4; q++)
                        CPA16(dstb + (uint32_t)(q * 16), xs + q * 16);
                    asm volatile("cp.async.commit_group;" ::: "memory");
                }

                // epilogue for this pr
#pragma unroll
                for (int ni = 0; ni < 4; ni++) {
                    int hc = ni * 8 + qc;
                    float2 bvA, bvB;
                    asm("ld.shared.v2.f32 {%0, %1}, [%2];"
                        : "=f"(bvA.x), "=f"(bvA.y)
                        : "r"(sbase + BIAS_OFF + (uint32_t)((gA * 32 + hc) * 4)));
                    if (hasB) {
                        asm("ld.shared.v2.f32 {%0, %1}, [%2];"
                            : "=f"(bvB.x), "=f"(bvB.y)
                            : "r"(sbase + BIAS_OFF
                                  + (uint32_t)(((gA + 1) * 32 + hc) * 4)));
                        uint32_t v0 = packh2(accA[ni][0] + bvA.x, accB[ni][0] + bvB.x);
                        uint32_t v1 = packh2(accA[ni][1] + bvA.y, accB[ni][1] + bvB.y);
                        uint32_t v2 = packh2(accA[ni][2] + bvA.x, accB[ni][2] + bvB.x);
                        uint32_t v3 = packh2(accA[ni][3] + bvA.y, accB[ni][3] + bvB.y);
                        uint32_t ad = s01 + (uint32_t)(pr * 2048 + qr * 128 + hc * 4);
                        STSV2(ad, v0, v1);
                        STSV2(ad + 1024u, v2, v3);
                    } else {
                        uint32_t v0 = packh2(accA[ni][0] + bvA.x, accA[ni][1] + bvA.y);
                        uint32_t v1 = packh2(accA[ni][2] + bvA.x, accA[ni][3] + bvA.y);
                        uint32_t ad = sc + (uint32_t)(qr * 64 + (hc >> 1) * 4);
                        STS32(ad, v0);
                        STS32(ad + 512u, v1);
                    }
                }
            }

            __syncwarp();
            if (lane == 0)
                ST_REL(sbase + GPROG_OFF + (uint32_t)(R * 4), 2 * P + 1);
        }
    }
}

// ================= launcher =================
extern "C" void kernel_launch(void* const* d_in, const int* in_sizes, int n_in,
                              void* d_out, int out_size) {
    (void)in_sizes; (void)n_in; (void)out_size;
    const float* x     = (const float*)d_in[0];
    const float* wf    = (const float*)d_in[1];
    const float* uf    = (const float*)d_in[2];
    const float* biasf = (const float*)d_in[3];
    const float* wi    = (const float*)d_in[4];
    const float* ui    = (const float*)d_in[5];
    const float* biasi = (const float*)d_in[6];
    const float* wo    = (const float*)d_in[7];
    const float* uo    = (const float*)d_in[8];
    const float* biaso = (const float*)d_in[9];
    const float* wc    = (const float*)d_in[10];
    const float* uc    = (const float*)d_in[11];
    const float* biasc = (const float*)d_in[12];
    float* out = (float*)d_out;

    xconv<<<4096, 512>>>(x);
    cudaFuncSetAttribute(mdlstm_fused,
                         cudaFuncAttributeMaxDynamicSharedMemorySize, SM_TOTAL);
    mdlstm_fused<<<128, THREADS, SM_TOTAL>>>(
        wf, uf, biasf, wi, ui, biasi, wo, uo, biaso, wc, uc, biasc, out);
}